// round 12
// baseline (speedup 1.0000x reference)
#include <cuda_runtime.h>

#define BS   256
#define FTN  8
#define ATN  264   // BS + FTN
#define NDIM 512

#define NBLK_A  (BS * BS / 8)    // 8192 blocks: square part, 1 a x 8 b per block
#define NBLK_B  (BS)             // 256 blocks: false part, 1 b x 8 f per block

// Accumulators (zero-initialized at module load; final kernel resets them
// after consuming, so every graph replay starts from zero).
__device__ float g_rowsum[BS];   // sum_a exp(L[b,a])
__device__ float g_colsum[BS];   // sum_b exp(L[b,a]), a < 256
__device__ float g_diagsum;      // sum_b L[b,b]

__device__ __forceinline__ float4 ldcs4(const float4* p) {
    float4 v;
    asm volatile("ld.global.cs.v4.f32 {%0,%1,%2,%3}, [%4];"
                 : "=f"(v.x), "=f"(v.y), "=f"(v.z), "=f"(v.w) : "l"(p));
    return v;
}
__device__ __forceinline__ float4 ldnc4(const float4* p) {
    float4 v;
    asm volatile("ld.global.nc.v4.f32 {%0,%1,%2,%3}, [%4];"
                 : "=f"(v.x), "=f"(v.y), "=f"(v.z), "=f"(v.w) : "l"(p));
    return v;
}

__device__ __forceinline__ void acc3(const float4& x, const float4& t,
                                     float& dot, float& in2, float& tn2)
{
    dot += x.x * t.x + x.y * t.y + x.z * t.z + x.w * t.w;
    in2 += x.x * x.x + x.y * x.y + x.z * x.z + x.w * x.w;
    tn2 += t.x * t.x + t.y * t.y + t.z * t.z + t.w * t.w;
}

// ---------------------------------------------------------------------------
// Kernel 1: fused dot + exp-accumulate.
//  Blocks [0, 8192):  square part. block -> (a, b-group of 8). The text row
//    rand[a] is staged in smem ONCE per block (cuts text L2 traffic 8x);
//    8 warps compute L[b0+wid, a] reading text from smem.
//  Blocks [8192, 8448): false part. block -> b; warp wid -> false row j=wid.
//  lane 0:  RED rowsum[b] += exp(L);  RED colsum[a] += exp(L) (square only);
//           RED diagsum += L (a == b).  No max needed: |L| <= e.
// ---------------------------------------------------------------------------
__global__ __launch_bounds__(256) void cl_dot_kernel(
    const float* __restrict__ img,
    const float* __restrict__ rand_t,
    const float* __restrict__ false_t,
    const float* __restrict__ logit_scale)
{
    __shared__ float4 s_text[NDIM / 4];   // 2 KB staged text row

    int wid  = threadIdx.x >> 5;
    int lane = threadIdx.x & 31;
    int bx   = blockIdx.x;

    if (bx < NBLK_A) {
        // ---- square part: a fixed per block, b = bg*8 + wid ----
        int a  = bx >> 5;             // 256 a values
        int bg = bx & 31;             // 32 b-groups
        int b  = bg * 8 + wid;

        // Stage text row in smem (threads 0..127 load one float4 each).
        const float4* tg = (const float4*)(rand_t + (size_t)a * NDIM);
        if (threadIdx.x < NDIM / 4)
            s_text[threadIdx.x] = ldnc4(tg + threadIdx.x);
        __syncthreads();

        const float4* ip = (const float4*)(img + ((size_t)b * ATN + a) * NDIM);
        float4 x0 = ldcs4(ip + lane);
        float4 x1 = ldcs4(ip + lane + 32);
        float4 x2 = ldcs4(ip + lane + 64);
        float4 x3 = ldcs4(ip + lane + 96);
        float4 t0 = s_text[lane];
        float4 t1 = s_text[lane + 32];
        float4 t2 = s_text[lane + 64];
        float4 t3 = s_text[lane + 96];

        float dot = 0.f, in2 = 0.f, tn2 = 0.f;
        acc3(x0, t0, dot, in2, tn2);
        acc3(x1, t1, dot, in2, tn2);
        acc3(x2, t2, dot, in2, tn2);
        acc3(x3, t3, dot, in2, tn2);

        #pragma unroll
        for (int o = 16; o > 0; o >>= 1) {
            dot += __shfl_xor_sync(0xffffffffu, dot, o);
            in2 += __shfl_xor_sync(0xffffffffu, in2, o);
            tn2 += __shfl_xor_sync(0xffffffffu, tn2, o);
        }
        if (lane == 0) {
            float scale = expf(logit_scale[0]);
            float lg = scale * dot * rsqrtf(in2 * tn2);
            float e  = expf(lg);                 // |lg| <= scale, no max needed
            atomicAdd(&g_rowsum[b], e);
            atomicAdd(&g_colsum[a], e);
            if (a == b) atomicAdd(&g_diagsum, lg);
        }
    } else {
        // ---- false part: b fixed per block, warp wid -> false row j = wid ----
        int b = bx - NBLK_A;
        int j = wid;

        const float4* ip = (const float4*)(img + ((size_t)b * ATN + BS + j) * NDIM);
        const float4* tp = (const float4*)(false_t + ((size_t)b * FTN + j) * NDIM);

        float4 x0 = ldcs4(ip + lane);
        float4 x1 = ldcs4(ip + lane + 32);
        float4 x2 = ldcs4(ip + lane + 64);
        float4 x3 = ldcs4(ip + lane + 96);
        float4 t0 = ldnc4(tp + lane);
        float4 t1 = ldnc4(tp + lane + 32);
        float4 t2 = ldnc4(tp + lane + 64);
        float4 t3 = ldnc4(tp + lane + 96);

        float dot = 0.f, in2 = 0.f, tn2 = 0.f;
        acc3(x0, t0, dot, in2, tn2);
        acc3(x1, t1, dot, in2, tn2);
        acc3(x2, t2, dot, in2, tn2);
        acc3(x3, t3, dot, in2, tn2);

        #pragma unroll
        for (int o = 16; o > 0; o >>= 1) {
            dot += __shfl_xor_sync(0xffffffffu, dot, o);
            in2 += __shfl_xor_sync(0xffffffffu, in2, o);
            tn2 += __shfl_xor_sync(0xffffffffu, tn2, o);
        }
        if (lane == 0) {
            float scale = expf(logit_scale[0]);
            float lg = scale * dot * rsqrtf(in2 * tn2);
            atomicAdd(&g_rowsum[b], expf(lg));   // false terms only feed image CE
        }
    }
}

// ---------------------------------------------------------------------------
// Kernel 2: single block.
//   loss = ( sum_b log rowsum[b] + sum_a log colsum[a] - 2*diagsum ) / 512
// Then reset the accumulators for the next graph replay.
// ---------------------------------------------------------------------------
__global__ __launch_bounds__(256) void cl_final_kernel(float* __restrict__ out)
{
    __shared__ float sd[256];
    int t = threadIdx.x;

    float rs = g_rowsum[t];
    float cs = g_colsum[t];
    sd[t] = logf(rs) + logf(cs);
    __syncthreads();
    #pragma unroll
    for (int s = 128; s > 0; s >>= 1) {
        if (t < s) sd[t] += sd[t + s];
        __syncthreads();
    }
    if (t == 0) {
        out[0] = (sd[0] - 2.0f * g_diagsum) * (1.0f / (2.0f * BS));
        g_diagsum = 0.0f;
    }
    // reset for next replay (value already consumed into sd)
    g_rowsum[t] = 0.0f;
    g_colsum[t] = 0.0f;
}

extern "C" void kernel_launch(void* const* d_in, const int* in_sizes, int n_in,
                              void* d_out, int out_size)
{
    const float* img     = (const float*)d_in[0];  // [256, 264, 512]
    const float* rand_t  = (const float*)d_in[1];  // [256, 512]
    const float* false_t = (const float*)d_in[2];  // [2048, 512]
    const float* lscale  = (const float*)d_in[3];  // [1]
    float* out = (float*)d_out;

    cl_dot_kernel<<<NBLK_A + NBLK_B, 256>>>(img, rand_t, false_t, lscale);
    cl_final_kernel<<<1, 256>>>(out);
}